// round 6
// baseline (speedup 1.0000x reference)
#include <cuda_runtime.h>

#define H      20
#define NEX    13
#define EMBD   3
#define FIN    3
#define FOUT   5
#define HIN    8
#define HID    10
#define BLK    128
#define ROWS_B 64         // rows per block (2 threads per row)
#define FROW   (H*FIN)    // 60 floats of f per row
#define WSTR   64         // per-head packed weight stride (floats)
#define ESTR   12         // E' row stride (floats) -> 48B
#define FSTR   62         // s_f row stride

typedef unsigned long long u64;

// g_E[(h*NEX+idx)*12 + j] = emb[idx]@W1[h][0:3,j] + b1[h][j] + bf@W1[h][3:8,j]  (j<10, pad 0)
// g_W[h*64 + c*12 + j] = (Wf @ W1[h][3:8])[c][j]  (c=0..2, j<10, pad 0)
// g_W[h*64 + 36+j] = 0.505*W2[h][j]   (p)
// g_W[h*64 + 48+j] = 0.495*W2[h][j]   (q)
// g_W[h*64 + 58] = b2[h];  [59] = Wo[h]
__device__ __align__(16) float g_E[H * NEX * ESTR];   // 3120 floats
__device__ __align__(16) float g_W[H * WSTR];         // 1280 floats

__global__ void prep_kernel(const float* __restrict__ emb,
                            const float* __restrict__ Wf,
                            const float* __restrict__ bf,
                            const float* __restrict__ W1,
                            const float* __restrict__ b1,
                            const float* __restrict__ W2,
                            const float* __restrict__ b2,
                            const float* __restrict__ Wo)
{
    const int g = blockIdx.x * blockDim.x + threadIdx.x;
    const int NE = H * NEX * ESTR;          // 3120
    if (g < NE) {
        const int h   = g / (NEX * ESTR);
        const int r   = g % (NEX * ESTR);
        const int idx = r / ESTR;
        const int j   = r % ESTR;
        float v = 0.0f;
        if (j < HID) {
            v = b1[h * HID + j];
#pragma unroll
            for (int k = 0; k < FOUT; k++)
                v = fmaf(bf[k], W1[(h * HIN + 3 + k) * HID + j], v);
#pragma unroll
            for (int d = 0; d < EMBD; d++)
                v = fmaf(emb[idx * EMBD + d], W1[(h * HIN + d) * HID + j], v);
        }
        g_E[g] = v;
    } else if (g < NE + H * WSTR) {
        const int w = g - NE;
        const int h = w / WSTR;
        const int j = w % WSTR;
        float v = 0.0f;
        if (j < 36) {
            const int c  = j / 12;
            const int jj = j % 12;
            if (jj < HID) {
#pragma unroll
                for (int k = 0; k < FOUT; k++)
                    v = fmaf(Wf[c * FOUT + k], W1[(h * HIN + 3 + k) * HID + jj], v);
            }
        } else if (j < 46) {
            v = 0.505f * W2[h * HID + (j - 36)];
        } else if (j >= 48 && j < 58) {
            v = 0.495f * W2[h * HID + (j - 48)];
        } else if (j == 58) {
            v = b2[h];
        } else if (j == 59) {
            v = Wo[h];
        }
        g_W[w] = v;
    }
}

__device__ __forceinline__ double ffma2(double a, double b, double c) {
    double d; asm("fma.rn.f32x2 %0, %1, %2, %3;" : "=d"(d) : "d"(a), "d"(b), "d"(c)); return d;
}
__device__ __forceinline__ double fadd2(double a, double b) {
    double d; asm("add.rn.f32x2 %0, %1, %2;" : "=d"(d) : "d"(a), "d"(b)); return d;
}
union D2 { double d; float2 f; u64 u; };
#define ABS2(x) ((x) & 0x7FFFFFFF7FFFFFFFULL)

__global__ __launch_bounds__(BLK, 6)
void airfit_main(const int*   __restrict__ e,
                 const float* __restrict__ f,
                 const float* __restrict__ bo,
                 float*       __restrict__ out,
                 int n)
{
    // 34752 bytes static shared -> 6 CTAs/SM
    __shared__ __align__(16) float        s_E[H * NEX * ESTR];   // 12480 B
    __shared__ __align__(16) float        s_W[H * WSTR];         //  5120 B
    __shared__ __align__(16) float        s_f[ROWS_B * FSTR];    // 15872 B
    __shared__              unsigned int  s_e[ROWS_B * H / 4];   //  1280 B

    const int tid  = threadIdx.x;
    const int lane = tid & 31;
    const int warp = tid >> 5;
    const int row_local = warp * 16 + (lane & 15);
    const int half = lane >> 4;                     // 0: heads 0-9, 1: heads 10-19

    const long long b0 = (long long)blockIdx.x * ROWS_B;
    const long long b  = b0 + row_local;
    const bool active = (b < n);

    int rows = n - (int)b0;
    if (rows > ROWS_B) rows = ROWS_B;
    if (rows < 0)      rows = 0;

    // ---- stage E' + W tables (uniform float4 copies) ----
    {
        const float4* srcE = reinterpret_cast<const float4*>(g_E);
        float4*       dstE = reinterpret_cast<float4*>(s_E);
        for (int i = tid; i < H * NEX * ESTR / 4; i += BLK) dstE[i] = srcE[i];
        const float4* srcW = reinterpret_cast<const float4*>(g_W);
        float4*       dstW = reinterpret_cast<float4*>(s_W);
        for (int i = tid; i < H * WSTR / 4; i += BLK) dstW[i] = srcW[i];
    }

    // ---- stage e coalesced: int4 loads, 4 indices packed per word ----
    {
        const int4* eg = reinterpret_cast<const int4*>(e + b0 * H);
        const int nv = rows * (H / 4);                 // rows*5 words
        for (int v = tid; v < nv; v += BLK) {
            int4 val = eg[v];
            s_e[v] = (unsigned)(val.x & 0xFF)
                   | ((unsigned)(val.y & 0xFF) << 8)
                   | ((unsigned)(val.z & 0xFF) << 16)
                   | ((unsigned)(val.w & 0xFF) << 24);
        }
    }

    // ---- stage f coalesced float4 -> stride-62 rows via STS.64 pairs ----
    {
        const float4* fg = reinterpret_cast<const float4*>(f + b0 * FROW);
        const int nf4 = rows * (FROW / 4);             // rows*15
        for (int v = tid; v < nf4; v += BLK) {
            float4 val = fg[v];
            const int row = v / 15;
            const int col = 4 * (v % 15);
            float2* dst = reinterpret_cast<float2*>(&s_f[row * FSTR + col]);
            dst[0] = make_float2(val.x, val.y);
            dst[1] = make_float2(val.z, val.w);
        }
    }
    __syncthreads();

    float acc = 0.0f;

    if (active) {
        const float* my_f = &s_f[row_local * FSTR + half * 30];
        const unsigned char* my_e =
            reinterpret_cast<const unsigned char*>(s_e) + row_local * H + half * 10;
        const int hbase = half * 10;

#pragma unroll
        for (int hh = 0; hh < 10; hh++) {
            const int h   = hbase + hh;
            const int idx = (int)my_e[hh];

            // accumulators from bias-folded embedding table
            const float* Ep = &s_E[(h * NEX + idx) * ESTR];
            const double2 ea = *reinterpret_cast<const double2*>(Ep);
            const double2 eb = *reinterpret_cast<const double2*>(Ep + 4);
            double t0 = ea.x, t1 = ea.y, t2 = eb.x, t3 = eb.y;
            double t4 = *reinterpret_cast<const double*>(Ep + 8);

            const float* Wh = &s_W[h * WSTR];
#pragma unroll
            for (int c = 0; c < 3; c++) {
                const float fc = my_f[hh * 3 + c];
                D2 fc2; fc2.f = make_float2(fc, fc);
                const double2 wa = *reinterpret_cast<const double2*>(Wh + c * 12);
                const double2 wb = *reinterpret_cast<const double2*>(Wh + c * 12 + 4);
                const double  wc = *reinterpret_cast<const double*>(Wh + c * 12 + 8);
                t0 = ffma2(fc2.d, wa.x, t0);
                t1 = ffma2(fc2.d, wa.y, t1);
                t2 = ffma2(fc2.d, wb.x, t2);
                t3 = ffma2(fc2.d, wb.y, t3);
                t4 = ffma2(fc2.d, wc,   t4);
            }

            // leaky+W2 fold: z = sum p_j*t_j + q_j*|t_j| + b2
            const double2 P0 = *reinterpret_cast<const double2*>(Wh + 36); // p0..3
            const double2 P1 = *reinterpret_cast<const double2*>(Wh + 40); // p4..7
            const double  P2 = *reinterpret_cast<const double*>(Wh + 44);  // p8,p9
            const double2 Q0 = *reinterpret_cast<const double2*>(Wh + 48); // q0..3
            const double2 Q1 = *reinterpret_cast<const double2*>(Wh + 52); // q4..7
            const double2 Q2 = *reinterpret_cast<const double2*>(Wh + 56); // q8,q9 | b2,Wo
            D2 tail; tail.d = Q2.y;                    // .f.x = b2, .f.y = Wo

            D2 za; za.f = make_float2(tail.f.x, 0.0f); // start p-chain with b2
            D2 zb; zb.u = 0;
            za.d = ffma2(t0, P0.x, za.d);
            za.d = ffma2(t1, P0.y, za.d);
            za.d = ffma2(t2, P1.x, za.d);
            za.d = ffma2(t3, P1.y, za.d);
            za.d = ffma2(t4, P2,   za.d);
            D2 a0, a1, a2, a3, a4;
            a0.d = t0; a1.d = t1; a2.d = t2; a3.d = t3; a4.d = t4;
            a0.u = ABS2(a0.u); a1.u = ABS2(a1.u); a2.u = ABS2(a2.u);
            a3.u = ABS2(a3.u); a4.u = ABS2(a4.u);
            zb.d = ffma2(a0.d, Q0.x, zb.d);
            zb.d = ffma2(a1.d, Q0.y, zb.d);
            zb.d = ffma2(a2.d, Q1.x, zb.d);
            zb.d = ffma2(a3.d, Q1.y, zb.d);
            zb.d = ffma2(a4.d, Q2.x, zb.d);

            D2 zs; zs.d = fadd2(za.d, zb.d);
            const float z = zs.f.x + zs.f.y;

            // softplus = max(z,0) + log1p(exp(-|z|))
            const float sp = fmaxf(z, 0.0f) + __logf(1.0f + __expf(-fabsf(z)));
            acc = fmaf(sp, tail.f.y, acc);             // * Wo
        }
    }

    // combine the two half-rows
    acc += __shfl_xor_sync(0xffffffffu, acc, 16);
    if (active && half == 0) out[b] = acc + __ldg(bo);
}

extern "C" void kernel_launch(void* const* d_in, const int* in_sizes, int n_in,
                              void* d_out, int out_size)
{
    const int*   e   = (const int*)  d_in[0];
    const float* f   = (const float*)d_in[1];
    const float* emb = (const float*)d_in[2];
    const float* Wf  = (const float*)d_in[3];
    const float* bf  = (const float*)d_in[4];
    const float* W1  = (const float*)d_in[5];
    const float* b1  = (const float*)d_in[6];
    const float* W2  = (const float*)d_in[7];
    const float* b2  = (const float*)d_in[8];
    const float* Wo  = (const float*)d_in[9];
    const float* bo  = (const float*)d_in[10];
    float* out = (float*)d_out;

    const int n = in_sizes[0] / H;

    const int prep_elems = H * NEX * ESTR + H * WSTR;  // 4400
    prep_kernel<<<(prep_elems + 255) / 256, 256>>>(emb, Wf, bf, W1, b1, W2, b2, Wo);

    const int grid = (n + ROWS_B - 1) / ROWS_B;
    airfit_main<<<grid, BLK>>>(e, f, bo, out, n);
}

// round 10
// speedup vs baseline: 1.3504x; 1.3504x over previous
#include <cuda_runtime.h>

#define H      20
#define NEX    13
#define EMBD   3
#define FIN    3
#define FOUT   5
#define HIN    8
#define HID    10
#define BLK    128
#define FROW   (H*FIN)    // 60 floats of f per row
#define WSTR   64         // per-head packed weight stride (floats)
#define ESTR   12         // E' row stride (floats) -> 48B, 16B-aligned rows
#define FSTR   61         // s_f row stride: odd -> conflict-free LDS.32

typedef unsigned long long u64;

// g_E[(h*NEX+idx)*12 + j] = emb[idx]@W1[h][0:3,j] + b1[h][j] + bf@W1[h][3:8,j]  (j<10, pad 0)
// g_W[h*64 + c*12 + j] = (Wf @ W1[h][3:8])[c][j]  (c=0..2, j<10, pad 0)
// g_W[h*64 + 36+j] = 0.505*W2[h][j]   (p)
// g_W[h*64 + 48+j] = 0.495*W2[h][j]   (q)
// g_W[h*64 + 58] = b2[h];  [59] = Wo[h]
__device__   __align__(16) float g_E[H * NEX * ESTR];   // 3120 floats
__device__   __align__(16) float g_W[H * WSTR];         // 1280 floats
__constant__ __align__(16) float c_W[H * WSTR];

__global__ void prep_kernel(const float* __restrict__ emb,
                            const float* __restrict__ Wf,
                            const float* __restrict__ bf,
                            const float* __restrict__ W1,
                            const float* __restrict__ b1,
                            const float* __restrict__ W2,
                            const float* __restrict__ b2,
                            const float* __restrict__ Wo)
{
    const int g = blockIdx.x * blockDim.x + threadIdx.x;
    const int NE = H * NEX * ESTR;          // 3120
    if (g < NE) {
        const int h   = g / (NEX * ESTR);
        const int r   = g % (NEX * ESTR);
        const int idx = r / ESTR;
        const int j   = r % ESTR;
        float v = 0.0f;
        if (j < HID) {
            v = b1[h * HID + j];
#pragma unroll
            for (int k = 0; k < FOUT; k++)
                v = fmaf(bf[k], W1[(h * HIN + 3 + k) * HID + j], v);
#pragma unroll
            for (int d = 0; d < EMBD; d++)
                v = fmaf(emb[idx * EMBD + d], W1[(h * HIN + d) * HID + j], v);
        }
        g_E[g] = v;
    } else if (g < NE + H * WSTR) {
        const int w = g - NE;
        const int h = w / WSTR;
        const int j = w % WSTR;
        float v = 0.0f;
        if (j < 36) {
            const int c  = j / 12;
            const int jj = j % 12;
            if (jj < HID) {
#pragma unroll
                for (int k = 0; k < FOUT; k++)
                    v = fmaf(Wf[c * FOUT + k], W1[(h * HIN + 3 + k) * HID + jj], v);
            }
        } else if (j < 46) {
            v = 0.505f * W2[h * HID + (j - 36)];
        } else if (j >= 48 && j < 58) {
            v = 0.495f * W2[h * HID + (j - 48)];
        } else if (j == 58) {
            v = b2[h];
        } else if (j == 59) {
            v = Wo[h];
        }
        g_W[w] = v;
    }
}

__device__ __forceinline__ double ffma2(double a, double b, double c) {
    double d; asm("fma.rn.f32x2 %0, %1, %2, %3;" : "=d"(d) : "d"(a), "d"(b), "d"(c)); return d;
}
__device__ __forceinline__ double fadd2(double a, double b) {
    double d; asm("add.rn.f32x2 %0, %1, %2;" : "=d"(d) : "d"(a), "d"(b)); return d;
}
union D2 { double d; float2 f; u64 u; };
#define ABS2(x) ((x) & 0x7FFFFFFF7FFFFFFFULL)

__global__ __launch_bounds__(BLK, 5)
void airfit_main(const int*   __restrict__ e,
                 const float* __restrict__ f,
                 const float* __restrict__ bo,
                 float*       __restrict__ out,
                 int n)
{
    // 45248 bytes static shared -> 5 CTAs/SM
    __shared__ __align__(16) float        s_E[H * NEX * ESTR];  // 12480 B
    __shared__              float         s_f[BLK * FSTR];      // 31232 B
    __shared__              unsigned int  s_e[BLK * 3];         //  1536 B (nibble-packed)

    const int tid = threadIdx.x;
    const long long b0 = (long long)blockIdx.x * BLK;
    const long long b  = b0 + tid;
    const bool active = (b < n);

    int rows = n - (int)b0;
    if (rows > BLK) rows = BLK;
    if (rows < 0)   rows = 0;

    // ---- stage E' (uniform float4 copies, 780 f4) ----
    {
        const float4* src = reinterpret_cast<const float4*>(g_E);
        float4*       dst = reinterpret_cast<float4*>(s_E);
        for (int i = tid; i < H * NEX * ESTR / 4; i += BLK) dst[i] = src[i];
    }

    // ---- stage e: coalesced int4 loads, 4-bit packed indices (idx < 13) ----
    {
        const int nv = rows * 3;                     // 3 words per row
        for (int v = tid; v < nv; v += BLK) {
            const int r = v / 3;
            const int w = v % 3;
            const int* ebase = e + (b0 + r) * H + w * 8;
            const int4 a = *reinterpret_cast<const int4*>(ebase);
            unsigned word = (unsigned)a.x | ((unsigned)a.y << 4)
                          | ((unsigned)a.z << 8) | ((unsigned)a.w << 12);
            if (w < 2) {
                const int4 c = *reinterpret_cast<const int4*>(ebase + 4);
                word |= ((unsigned)c.x << 16) | ((unsigned)c.y << 20)
                      | ((unsigned)c.z << 24) | ((unsigned)c.w << 28);
            }
            s_e[r * 3 + w] = word;
        }
    }

    // ---- stage f coalesced float4 -> stride-61 rows ----
    {
        const float4* fg = reinterpret_cast<const float4*>(f + b0 * FROW);
        const int nf4 = rows * (FROW / 4);           // rows*15
        for (int v = tid; v < nf4; v += BLK) {
            float4 val = fg[v];
            const int row = v / 15;
            const int col = 4 * (v % 15);
            float* dst = &s_f[row * FSTR + col];
            dst[0] = val.x; dst[1] = val.y; dst[2] = val.z; dst[3] = val.w;
        }
    }
    __syncthreads();

    if (active) {
        // prefetch this row's 20 nibble-packed indices into 3 registers
        unsigned ew[3];
#pragma unroll
        for (int c = 0; c < 3; c++) ew[c] = s_e[tid * 3 + c];

        const float* my_f = &s_f[tid * FSTR];
        float accA = __ldg(bo);
        float accB = 0.0f;

#pragma unroll
        for (int h = 0; h < H; h++) {
            const int idx = (int)((ew[h >> 3] >> ((h & 7) * 4)) & 0xF);

            // accumulators from bias-folded embedding table (LDS.128 x2 + LDS.64)
            const float* Ep = &s_E[(h * NEX + idx) * ESTR];
            const double2 ea = *reinterpret_cast<const double2*>(Ep);
            const double2 eb = *reinterpret_cast<const double2*>(Ep + 4);
            double t0 = ea.x, t1 = ea.y, t2 = eb.x, t3 = eb.y;
            double t4 = *reinterpret_cast<const double*>(Ep + 8);

            const float* Wh = &c_W[h * WSTR];
#pragma unroll
            for (int c = 0; c < 3; c++) {
                const float fc = my_f[h * 3 + c];
                D2 fc2; fc2.f = make_float2(fc, fc);
                const double2 wa = *reinterpret_cast<const double2*>(Wh + c * 12);
                const double2 wb = *reinterpret_cast<const double2*>(Wh + c * 12 + 4);
                const double  wc = *reinterpret_cast<const double*>(Wh + c * 12 + 8);
                t0 = ffma2(fc2.d, wa.x, t0);
                t1 = ffma2(fc2.d, wa.y, t1);
                t2 = ffma2(fc2.d, wb.x, t2);
                t3 = ffma2(fc2.d, wb.y, t3);
                t4 = ffma2(fc2.d, wc,   t4);
            }

            // leaky+W2 fold: z = sum p_j*t_j + q_j*|t_j| + b2
            const double2 P0 = *reinterpret_cast<const double2*>(Wh + 36);
            const double2 P1 = *reinterpret_cast<const double2*>(Wh + 40);
            const double  P2 = *reinterpret_cast<const double*>(Wh + 44);
            const double2 Q0 = *reinterpret_cast<const double2*>(Wh + 48);
            const double2 Q1 = *reinterpret_cast<const double2*>(Wh + 52);
            const double2 Q2 = *reinterpret_cast<const double2*>(Wh + 56); // q8,q9 | b2,Wo
            D2 tail; tail.d = Q2.y;                  // .f.x = b2, .f.y = Wo

            D2 za; za.f = make_float2(tail.f.x, 0.0f);
            D2 zb; zb.u = 0;
            za.d = ffma2(t0, P0.x, za.d);
            za.d = ffma2(t1, P0.y, za.d);
            za.d = ffma2(t2, P1.x, za.d);
            za.d = ffma2(t3, P1.y, za.d);
            za.d = ffma2(t4, P2,   za.d);
            D2 a0, a1, a2, a3, a4;
            a0.d = t0; a1.d = t1; a2.d = t2; a3.d = t3; a4.d = t4;
            a0.u = ABS2(a0.u); a1.u = ABS2(a1.u); a2.u = ABS2(a2.u);
            a3.u = ABS2(a3.u); a4.u = ABS2(a4.u);
            zb.d = ffma2(a0.d, Q0.x, zb.d);
            zb.d = ffma2(a1.d, Q0.y, zb.d);
            zb.d = ffma2(a2.d, Q1.x, zb.d);
            zb.d = ffma2(a3.d, Q1.y, zb.d);
            zb.d = ffma2(a4.d, Q2.x, zb.d);

            D2 zs; zs.d = fadd2(za.d, zb.d);
            const float z = zs.f.x + zs.f.y;

            // softplus = max(z,0) + log1p(exp(-|z|))
            const float sp = fmaxf(z, 0.0f) + __logf(1.0f + __expf(-fabsf(z)));
            if (h & 1) accB = fmaf(sp, tail.f.y, accB);
            else       accA = fmaf(sp, tail.f.y, accA);
        }

        out[b] = accA + accB;
    }
}

extern "C" void kernel_launch(void* const* d_in, const int* in_sizes, int n_in,
                              void* d_out, int out_size)
{
    const int*   e   = (const int*)  d_in[0];
    const float* f   = (const float*)d_in[1];
    const float* emb = (const float*)d_in[2];
    const float* Wf  = (const float*)d_in[3];
    const float* bf  = (const float*)d_in[4];
    const float* W1  = (const float*)d_in[5];
    const float* b1  = (const float*)d_in[6];
    const float* W2  = (const float*)d_in[7];
    const float* b2  = (const float*)d_in[8];
    const float* Wo  = (const float*)d_in[9];
    const float* bo  = (const float*)d_in[10];
    float* out = (float*)d_out;

    const int n = in_sizes[0] / H;

    const int prep_elems = H * NEX * ESTR + H * WSTR;   // 4400
    prep_kernel<<<(prep_elems + 255) / 256, 256>>>(emb, Wf, bf, W1, b1, W2, b2, Wo);

    void* gW_dev = nullptr;
    cudaGetSymbolAddress(&gW_dev, g_W);
    cudaMemcpyToSymbolAsync(c_W, gW_dev, sizeof(float) * H * WSTR, 0,
                            cudaMemcpyDeviceToDevice, 0);

    const int grid = (n + BLK - 1) / BLK;
    airfit_main<<<grid, BLK>>>(e, f, bo, out, n);
}